// round 7
// baseline (speedup 1.0000x reference)
#include <cuda_runtime.h>

#define BB 8
#define LL 4096
#define DD 1024
#define MAXW 720
#define CH 8               // channels per MA block
#define TILE 1024          // output timesteps per block
#define HALO 768           // >= MAXW-1, multiple of 256
#define SPAN (TILE + HALO) // 1792 = 7 * 256
#define PAD 1800           // row stride (floats); PAD % 8 == 0+? -> see bank notes
// PAD must be ≡ 4 (mod 8) so that 4*PAD ≡ 16 (mod 32): choose 1796.
#undef PAD
#define PAD 1796

// ---------------------------------------------------------------------------
// Moving-average half via LOCAL prefix sums, all-wide smem traffic.
//   y[t] = (S[t]-S[t-1]) + m1*(S[t]-S[t-w]),  m1 = -1/w
// ---------------------------------------------------------------------------
__global__ __launch_bounds__(256, 3) void ma_kernel(const float* __restrict__ u,
                                                    const float* __restrict__ ma_k,
                                                    float* __restrict__ out) {
    extern __shared__ float sm[];
    float* tile = sm;                       // CH * PAD floats (x -> S -> y in place)

    const int tid  = threadIdx.x;
    const int warp = tid >> 5;
    const int lane = tid & 31;
    const int grp  = blockIdx.x;                  // 0..63 : 8-channel group
    const int lt   = blockIdx.y;                  // L-tile (0..3)
    const int b    = blockIdx.z;
    const int g32  = 2 * (grp >> 2) + 1;          // odd 32-channel group
    const int d0   = g32 * 32 + (grp & 3) * 8;
    const int T0   = lt * TILE;

    const float4* u4 = (const float4*)u;
    float4*       o4 = (float4*)out;
    const size_t base4 = (size_t)b * LL * (DD / 4) + (d0 >> 2);

    const int c4 = tid & 1;          // float4 column (8 ch = 2 float4)
    const int gq = tid >> 1;         // quad-row group 0..127

    // ---- Phase A: load 4 rows/thread, register transpose, STS.128 quads ----
    {
        #pragma unroll
        for (int k = 0; k < 3; k++) {
            const int r4 = gq * 4 + k * 512;     // rows [k*512, k*512+512)
            float4 f[4];
            #pragma unroll
            for (int j = 0; j < 4; j++) {
                const int t = T0 - HALO + r4 + j;
                f[j] = (t >= 0) ? u4[base4 + (size_t)t * (DD / 4) + c4]
                                : make_float4(0.f, 0.f, 0.f, 0.f);
            }
            #pragma unroll
            for (int j = 0; j < 4; j++) {
                float4 q = make_float4(((const float*)&f[0])[j], ((const float*)&f[1])[j],
                                       ((const float*)&f[2])[j], ((const float*)&f[3])[j]);
                *(float4*)(tile + (c4 * 4 + j) * PAD + r4) = q;
            }
        }
        // tail rows [1536, 1792): 128 tasks
        if (tid < 128) {
            const int c4t = tid & 1;
            const int r4  = 1536 + (tid >> 1) * 4;
            float4 f[4];
            #pragma unroll
            for (int j = 0; j < 4; j++) {
                const int t = T0 - HALO + r4 + j;
                f[j] = (t >= 0) ? u4[base4 + (size_t)t * (DD / 4) + c4t]
                                : make_float4(0.f, 0.f, 0.f, 0.f);
            }
            #pragma unroll
            for (int j = 0; j < 4; j++) {
                float4 q = make_float4(((const float*)&f[0])[j], ((const float*)&f[1])[j],
                                       ((const float*)&f[2])[j], ((const float*)&f[3])[j]);
                *(float4*)(tile + (c4t * 4 + j) * PAD + r4) = q;
            }
        }
    }
    __syncthreads();

    // ---- Phase B: warp w scans channel w in place (7 sub-scans of 256) ----
    {
        float* trow = tile + warp * PAD;
        float carry = 0.0f;
        #pragma unroll
        for (int s = 0; s < SPAN / 256; s++) {
            float4 a  = *(const float4*)(trow + s * 256 + lane * 8);
            float4 bq = *(const float4*)(trow + s * 256 + lane * 8 + 4);
            float p0 = a.x,       p1 = p0 + a.y,  p2 = p1 + a.z,  p3 = p2 + a.w;
            float p4 = p3 + bq.x, p5 = p4 + bq.y, p6 = p5 + bq.z, p7 = p6 + bq.w;
            float v = p7;
            #pragma unroll
            for (int off = 1; off < 32; off <<= 1) {
                const float n = __shfl_up_sync(0xffffffffu, v, off);
                if (lane >= off) v += n;
            }
            const float bs = (v - p7) + carry;
            a.x = p0 + bs; a.y = p1 + bs; a.z = p2 + bs; a.w = p3 + bs;
            bq.x = p4 + bs; bq.y = p5 + bs; bq.z = p6 + bs; bq.w = p7 + bs;
            *(float4*)(trow + s * 256 + lane * 8)     = a;
            *(float4*)(trow + s * 256 + lane * 8 + 4) = bq;
            carry += __shfl_sync(0xffffffffu, v, 31);
        }
    }
    __syncthreads();

    // ---- Phase C-compute: warp w -> channel w, quads in DECREASING t,
    //      y overwrites S in place ----
    {
        float* trow = tile + warp * PAD;
        const int d = d0 + warp;
        const int i_ma = ((d >> 6) << 2) + ((d >> 3) & 7) - 4;   // 0..63
        const float m1 = __ldg(&ma_k[i_ma * MAXW + 1]);          // = -1/w
        const int  w   = (int)rintf(-1.0f / m1);
        const int  dlt = (-w) & 3;                               // (hr-w) mod 4

        #pragma unroll
        for (int i = TILE / 128 - 1; i >= 0; i--) {
            const int hr = HALO + i * 128 + lane * 4;
            const float4 S = *(const float4*)(trow + hr);
            float smw = __shfl_up_sync(0xffffffffu, S.w, 1);
            if (lane == 0) smw = trow[hr - 1];
            const int al = (hr - w) & ~3;
            const float4 lo = *(const float4*)(trow + al);
            const float4 hi = *(const float4*)(trow + al + 4);
            float4 so;
            if      (dlt == 0) so = lo;
            else if (dlt == 1) so = make_float4(lo.y, lo.z, lo.w, hi.x);
            else if (dlt == 2) so = make_float4(lo.z, lo.w, hi.x, hi.y);
            else               so = make_float4(lo.w, hi.x, hi.y, hi.z);
            float4 y;
            y.x = fmaf(m1, S.x - so.x, S.x - smw);
            y.y = fmaf(m1, S.y - so.y, S.y - S.x);
            y.z = fmaf(m1, S.z - so.z, S.z - S.y);
            y.w = fmaf(m1, S.w - so.w, S.w - S.z);
            __syncwarp();                       // all reads before any write
            *(float4*)(trow + hr) = y;
            __syncwarp();
        }
    }
    __syncthreads();

    // ---- Phase C-store: read channel quads, register transpose, STG.128 ----
    {
        #pragma unroll
        for (int it = 0; it < 2; it++) {
            const int r4 = gq * 4 + it * 512;    // output rows [0, 1024)
            float4 q[4];
            #pragma unroll
            for (int j = 0; j < 4; j++)
                q[j] = *(const float4*)(tile + (c4 * 4 + j) * PAD + HALO + r4);
            #pragma unroll
            for (int j = 0; j < 4; j++) {
                float4 o = make_float4(((const float*)&q[0])[j], ((const float*)&q[1])[j],
                                       ((const float*)&q[2])[j], ((const float*)&q[3])[j]);
                o4[base4 + (size_t)(T0 + r4 + j) * (DD / 4) + c4] = o;
            }
        }
    }
}

// ---------------------------------------------------------------------------
// Differencing half: even 32-channel groups, 4-tap causal stencil (R2 best).
// ---------------------------------------------------------------------------
__global__ __launch_bounds__(256) void diff_stencil_kernel(const float* __restrict__ u,
                                                           const float* __restrict__ dk,
                                                           float* __restrict__ out) {
    const int g  = blockIdx.x;                        // 0..15
    const int d  = g * 64 + threadIdx.x;              // 32 channels, even 32-group
    const int b  = blockIdx.z;
    const int t0 = (blockIdx.y * 8 + threadIdx.y) * 16;

    const int nk = (d >> 3) & 3;
    const float c0 = dk[nk * 4 + 0];
    const float c1 = dk[nk * 4 + 1];
    const float c2 = dk[nk * 4 + 2];
    const float c3 = dk[nk * 4 + 3];

    const size_t base = (size_t)b * LL * DD + d;

    float x1 = (t0 >= 1) ? u[base + (size_t)(t0 - 1) * DD] : 0.0f;
    float x2 = (t0 >= 2) ? u[base + (size_t)(t0 - 2) * DD] : 0.0f;
    float x3 = (t0 >= 3) ? u[base + (size_t)(t0 - 3) * DD] : 0.0f;

    #pragma unroll
    for (int tt = 0; tt < 16; tt++) {
        const int t = t0 + tt;
        const float x0 = u[base + (size_t)t * DD];
        out[base + (size_t)t * DD] = c0 * x0 + c1 * x1 + c2 * x2 + c3 * x3;
        x3 = x2; x2 = x1; x1 = x0;
    }
}

extern "C" void kernel_launch(void* const* d_in, const int* in_sizes, int n_in,
                              void* d_out, int out_size) {
    const float* u  = (const float*)d_in[0];   // (B, L, D)
    const float* dk = (const float*)d_in[1];   // (64, 4)
    const float* mk = (const float*)d_in[2];   // (64, 720)
    float* out = (float*)d_out;                // (B, L, D)

    const size_t smem = (size_t)(CH * PAD) * sizeof(float);   // 57,472 B
    cudaFuncSetAttribute(ma_kernel, cudaFuncAttributeMaxDynamicSharedMemorySize, (int)smem);

    // diff first, MA second: ncu (-s 5 -c 1) captures the 2nd launch -> profiles MA
    diff_stencil_kernel<<<dim3(16, 32, BB), dim3(32, 8)>>>(u, dk, out);
    ma_kernel<<<dim3(64, 4, BB), 256, smem>>>(u, mk, out);
}

// round 8
// speedup vs baseline: 1.0434x; 1.0434x over previous
#include <cuda_runtime.h>

#define BB 8
#define LL 4096
#define DD 1024
#define MAXW 720
#define CH 8               // channels per MA block
#define TILE 1024          // MA output timesteps per block
#define HALO 768           // >= MAXW-1
#define SPAN (TILE + HALO) // 1792 = 7 * 256
#define PAD 1796           // row stride: 4*PAD % 32 == 16 -> conflict-free pairs

#define N_DIFF 4096        // diff sub-blocks (16 x 32 x 8)
#define N_MA   2048        // MA  sub-blocks (64 x 4 x 8)

// ---------------------------------------------------------------------------
// Fused kernel: blockIdx.x % 3 == 2 -> MA body, else -> diff body.
// Interleaving spreads diff blocks across the MA execution window so diff's
// DRAM traffic overlaps MA's L1/latency phases.
// ---------------------------------------------------------------------------
__global__ __launch_bounds__(256, 3) void fused_kernel(const float* __restrict__ u,
                                                       const float* __restrict__ dk,
                                                       const float* __restrict__ ma_k,
                                                       float* __restrict__ out) {
    const int m = blockIdx.x % 3;
    const int q = blockIdx.x / 3;
    const int tid  = threadIdx.x;
    const int warp = tid >> 5;
    const int lane = tid & 31;

    if (m != 2) {
        // =============== diff body: 4-tap causal stencil =================
        const int id = q * 2 + m;              // 0..4095
        const int g  = id & 15;
        const int gy = (id >> 4) & 31;
        const int b  = id >> 9;

        const int d  = g * 64 + lane;          // even 32-channel group
        const int t0 = (gy * 8 + warp) * 16;

        const int nk = (d >> 3) & 3;
        const float c0 = dk[nk * 4 + 0];
        const float c1 = dk[nk * 4 + 1];
        const float c2 = dk[nk * 4 + 2];
        const float c3 = dk[nk * 4 + 3];

        const size_t base = (size_t)b * LL * DD + d;

        float x1 = (t0 >= 1) ? u[base + (size_t)(t0 - 1) * DD] : 0.0f;
        float x2 = (t0 >= 2) ? u[base + (size_t)(t0 - 2) * DD] : 0.0f;
        float x3 = (t0 >= 3) ? u[base + (size_t)(t0 - 3) * DD] : 0.0f;

        #pragma unroll
        for (int tt = 0; tt < 16; tt++) {
            const int t = t0 + tt;
            const float x0 = u[base + (size_t)t * DD];
            out[base + (size_t)t * DD] = c0 * x0 + c1 * x1 + c2 * x2 + c3 * x3;
            x3 = x2; x2 = x1; x1 = x0;
        }
        return;
    }

    // =============== MA body: local prefix-sum tiles =====================
    extern __shared__ float sm[];
    float* tile = sm;                          // CH * PAD floats

    const int grp = q & 63;                    // 8-channel group
    const int lt  = (q >> 6) & 3;              // L-tile 0..3
    const int b   = q >> 8;                    // batch
    const int g32 = 2 * (grp >> 2) + 1;        // odd 32-channel group
    const int d0  = g32 * 32 + (grp & 3) * 8;
    const int T0  = lt * TILE;

    const float4* u4 = (const float4*)u;
    float4*       o4 = (float4*)out;
    const size_t base4 = (size_t)b * LL * (DD / 4) + (d0 >> 2);

    const int c4 = tid & 1;          // float4 column (8 ch = 2 float4)
    const int gq = tid >> 1;         // quad-row group 0..127

    // ---- Phase A: load 4 rows/thread, register transpose, STS.128 ----
    {
        #pragma unroll
        for (int k = 0; k < 3; k++) {
            const int r4 = gq * 4 + k * 512;
            float4 f[4];
            #pragma unroll
            for (int j = 0; j < 4; j++) {
                const int t = T0 - HALO + r4 + j;
                f[j] = (t >= 0) ? u4[base4 + (size_t)t * (DD / 4) + c4]
                                : make_float4(0.f, 0.f, 0.f, 0.f);
            }
            #pragma unroll
            for (int j = 0; j < 4; j++) {
                float4 qv = make_float4(((const float*)&f[0])[j], ((const float*)&f[1])[j],
                                        ((const float*)&f[2])[j], ((const float*)&f[3])[j]);
                *(float4*)(tile + (c4 * 4 + j) * PAD + r4) = qv;
            }
        }
        if (tid < 128) {
            const int c4t = tid & 1;
            const int r4  = 1536 + (tid >> 1) * 4;
            float4 f[4];
            #pragma unroll
            for (int j = 0; j < 4; j++) {
                const int t = T0 - HALO + r4 + j;
                f[j] = (t >= 0) ? u4[base4 + (size_t)t * (DD / 4) + c4t]
                                : make_float4(0.f, 0.f, 0.f, 0.f);
            }
            #pragma unroll
            for (int j = 0; j < 4; j++) {
                float4 qv = make_float4(((const float*)&f[0])[j], ((const float*)&f[1])[j],
                                        ((const float*)&f[2])[j], ((const float*)&f[3])[j]);
                *(float4*)(tile + (c4t * 4 + j) * PAD + r4) = qv;
            }
        }
    }
    __syncthreads();

    // ---- Phase B: warp w scans channel w in place ----
    {
        float* trow = tile + warp * PAD;
        float carry = 0.0f;
        #pragma unroll
        for (int s = 0; s < SPAN / 256; s++) {
            float4 a  = *(const float4*)(trow + s * 256 + lane * 8);
            float4 bq = *(const float4*)(trow + s * 256 + lane * 8 + 4);
            float p0 = a.x,       p1 = p0 + a.y,  p2 = p1 + a.z,  p3 = p2 + a.w;
            float p4 = p3 + bq.x, p5 = p4 + bq.y, p6 = p5 + bq.z, p7 = p6 + bq.w;
            float v = p7;
            #pragma unroll
            for (int off = 1; off < 32; off <<= 1) {
                const float n = __shfl_up_sync(0xffffffffu, v, off);
                if (lane >= off) v += n;
            }
            const float bs = (v - p7) + carry;
            a.x = p0 + bs; a.y = p1 + bs; a.z = p2 + bs; a.w = p3 + bs;
            bq.x = p4 + bs; bq.y = p5 + bs; bq.z = p6 + bs; bq.w = p7 + bs;
            *(float4*)(trow + s * 256 + lane * 8)     = a;
            *(float4*)(trow + s * 256 + lane * 8 + 4) = bq;
            carry += __shfl_sync(0xffffffffu, v, 31);
        }
    }
    __syncthreads();

    // ---- Phase C-compute: warp w -> channel w, decreasing t, y over S ----
    {
        float* trow = tile + warp * PAD;
        const int d = d0 + warp;
        const int i_ma = ((d >> 6) << 2) + ((d >> 3) & 7) - 4;   // 0..63
        const float m1 = __ldg(&ma_k[i_ma * MAXW + 1]);          // = -1/w
        const int  w   = (int)rintf(-1.0f / m1);
        const int  dlt = (-w) & 3;

        #pragma unroll
        for (int i = TILE / 128 - 1; i >= 0; i--) {
            const int hr = HALO + i * 128 + lane * 4;
            const float4 S = *(const float4*)(trow + hr);
            float smw = __shfl_up_sync(0xffffffffu, S.w, 1);
            if (lane == 0) smw = trow[hr - 1];
            const int al = (hr - w) & ~3;
            const float4 lo = *(const float4*)(trow + al);
            const float4 hi = *(const float4*)(trow + al + 4);
            float4 so;
            if      (dlt == 0) so = lo;
            else if (dlt == 1) so = make_float4(lo.y, lo.z, lo.w, hi.x);
            else if (dlt == 2) so = make_float4(lo.z, lo.w, hi.x, hi.y);
            else               so = make_float4(lo.w, hi.x, hi.y, hi.z);
            float4 y;
            y.x = fmaf(m1, S.x - so.x, S.x - smw);
            y.y = fmaf(m1, S.y - so.y, S.y - S.x);
            y.z = fmaf(m1, S.z - so.z, S.z - S.y);
            y.w = fmaf(m1, S.w - so.w, S.w - S.z);
            __syncwarp();                       // all reads before any write
            *(float4*)(trow + hr) = y;
            __syncwarp();
        }
    }
    __syncthreads();

    // ---- Phase C-store: LDS.128 quads, register transpose, STG.128 ----
    {
        #pragma unroll
        for (int it = 0; it < 2; it++) {
            const int r4 = gq * 4 + it * 512;
            float4 qv[4];
            #pragma unroll
            for (int j = 0; j < 4; j++)
                qv[j] = *(const float4*)(tile + (c4 * 4 + j) * PAD + HALO + r4);
            #pragma unroll
            for (int j = 0; j < 4; j++) {
                float4 o = make_float4(((const float*)&qv[0])[j], ((const float*)&qv[1])[j],
                                       ((const float*)&qv[2])[j], ((const float*)&qv[3])[j]);
                o4[base4 + (size_t)(T0 + r4 + j) * (DD / 4) + c4] = o;
            }
        }
    }
}

extern "C" void kernel_launch(void* const* d_in, const int* in_sizes, int n_in,
                              void* d_out, int out_size) {
    const float* u  = (const float*)d_in[0];   // (B, L, D)
    const float* dk = (const float*)d_in[1];   // (64, 4)
    const float* mk = (const float*)d_in[2];   // (64, 720)
    float* out = (float*)d_out;                // (B, L, D)

    const size_t smem = (size_t)(CH * PAD) * sizeof(float);   // 57,472 B
    cudaFuncSetAttribute(fused_kernel, cudaFuncAttributeMaxDynamicSharedMemorySize, (int)smem);

    fused_kernel<<<N_DIFF + N_MA, 256, smem>>>(u, dk, mk, out);
}